// round 12
// baseline (speedup 1.0000x reference)
#include <cuda_runtime.h>
#include <cuda_fp16.h>
#include <cstdint>
#include <math.h>
#include <float.h>

#define NPAIR 1024
#define NOBJ  32

// m = i*30 + j (pool1 30x30 grid). Valid outputs i,j <= 25 -> m <= 775. 49 m16-tiles.
// Cluster of 3 CTAs per pair, split by pool-output rows (pi): 5/4/4 rows.
//   rank0: pi 0..4  (i 0..9)   m' in [0,296)   tiles 0..18   Xt rows 0..427   (428)
//   rank1: pi 5..8  (i 10..17) m' in [300,536) tiles 18..33  Xt rows 288..667 (380)
//   rank2: pi 9..12 (i 18..25) m' in [540,776) tiles 33..48  Xt rows 528..899 (372)
#define V_BYTES   (441 * 64 * 2)            // 56448: class LUT worst case
#define XT_MAX    (428 * 128)               // 54784
#define DSMEM     (V_BYTES + XT_MAX)        // 111232
// temp P tables live inside the Xt region during V build (P dead before Xt build).
// Y (86528B, global-indexed [o][676]) overlays [V..Xt] after the mainloop.

// ---------------- persistent prep scratch ----------------
__device__ float g_P[128 * 36];                        // conv1 SAT per (outch*2+box)
__device__ __align__(16) uint4 g_wF4[25 * 4 * 2 * 32]; // B-fragments [tap][kt][nt2][lane]

// ---------------- helpers ----------------
__device__ __forceinline__ uint32_t smem_u32(const void* p) {
    uint32_t a;
    asm("{ .reg .u64 t; cvta.to.shared.u64 t, %1; cvt.u32.u64 %0, t; }" : "=r"(a) : "l"(p));
    return a;
}
__device__ __forceinline__ uint32_t ctarank() {
    uint32_t r;
    asm("mov.u32 %0, %%cluster_ctarank;" : "=r"(r));
    return r;
}
__device__ __forceinline__ void st_cluster_f32(uint32_t local_addr, uint32_t target, float v) {
    uint32_t rem;
    asm("mapa.shared::cluster.u32 %0, %1, %2;" : "=r"(rem) : "r"(local_addr), "r"(target));
    asm volatile("st.shared::cluster.f32 [%0], %1;" :: "r"(rem), "f"(v) : "memory");
}
#define CLUSTER_SYNC() do { \
    asm volatile("barrier.cluster.arrive.aligned;" ::: "memory"); \
    asm volatile("barrier.cluster.wait.aligned;" ::: "memory"); } while (0)

__device__ __forceinline__ void ldsm_x4(uint32_t* a, uint32_t addr) {
    asm volatile("ldmatrix.sync.aligned.m8n8.x4.shared.b16 {%0,%1,%2,%3}, [%4];"
                 : "=r"(a[0]), "=r"(a[1]), "=r"(a[2]), "=r"(a[3]) : "r"(addr));
}
__device__ __forceinline__ void mma16816(float* d, const uint32_t* a, uint32_t b0, uint32_t b1) {
    asm volatile("mma.sync.aligned.m16n8k16.row.col.f32.f16.f16.f32 "
                 "{%0,%1,%2,%3}, {%4,%5,%6,%7}, {%8,%9}, {%0,%1,%2,%3};"
                 : "+f"(d[0]), "+f"(d[1]), "+f"(d[2]), "+f"(d[3])
                 : "r"(a[0]), "r"(a[1]), "r"(a[2]), "r"(a[3]), "r"(b0), "r"(b1));
}

// --------- exact integerization of mask intervals (proven) -----------
__device__ __forceinline__ int lo_int(float t) {
    int a = (int)ceilf(t - 0.5f);
    if ((float)a + 0.5f < t) a++;
    else if ((float)(a - 1) + 0.5f >= t) a--;
    return a;
}
__device__ __forceinline__ int hi_int(float t) {
    int b = (int)floorf(t - 0.5f);
    if ((float)b + 0.5f > t) b--;
    else if ((float)(b + 1) + 0.5f <= t) b++;
    return b;
}

// ---------------- K0: prep (unchanged, proven) ----------------
__global__ void prep_kernel(const float* __restrict__ conv2_w,
                            const float* __restrict__ conv1_w) {
    int idx = blockIdx.x * blockDim.x + threadIdx.x;
    if (idx < 6400) {
        int lane = idx & 31;
        int nt2  = (idx >> 5) & 1;
        int kt   = (idx >> 6) & 3;
        int tap  = idx >> 8;
        int c0 = kt * 16 + 2 * (lane & 3);
        int orow = lane >> 2;
        auto wv = [&](int o, int c) -> __half {
            return __float2half(conv2_w[(o * 64 + c) * 25 + tap]);
        };
        auto pk = [&](__half lo, __half hi) -> uint32_t {
            __half2 h = __halves2half2(lo, hi);
            return *(uint32_t*)&h;
        };
        int oe = (nt2 * 2) * 8 + orow;
        int oo = (nt2 * 2 + 1) * 8 + orow;
        uint4 u;
        u.x = pk(wv(oe, c0),     wv(oe, c0 + 1));
        u.y = pk(wv(oe, c0 + 8), wv(oe, c0 + 9));
        u.z = pk(wv(oo, c0),     wv(oo, c0 + 1));
        u.w = pk(wv(oo, c0 + 8), wv(oo, c0 + 9));
        g_wF4[((tap * 4 + kt) * 2 + nt2) * 32 + lane] = u;
    } else if (idx < 6400 + 128) {
        int u = idx - 6400;
        const float* w = conv1_w + u * 25;
        float P[36];
        #pragma unroll
        for (int k = 0; k < 6; k++) { P[k] = 0.0f; P[k * 6] = 0.0f; }
        for (int a = 1; a < 6; a++)
            for (int b = 1; b < 6; b++)
                P[a * 6 + b] = P[(a - 1) * 6 + b] + P[a * 6 + b - 1]
                             - P[(a - 1) * 6 + b - 1] + w[(a - 1) * 5 + (b - 1)];
        for (int k = 0; k < 36; k++) g_P[u * 36 + k] = P[k];
    }
}

// ---------------- K1: fused, 3-CTA clusters, 2 CTAs/SM ----------------
__global__ __launch_bounds__(512, 2) __cluster_dims__(3, 1, 1)
void fused_kernel(
    const float* __restrict__ bboxes, const int* __restrict__ object_pairs,
    const float* __restrict__ conv1_b, const float* __restrict__ conv2_b,
    const float* __restrict__ fc_w, const float* __restrict__ fc_b,
    float* __restrict__ out) {
    extern __shared__ char sm[];
    __half* Vh  = (__half*)sm;                        // [cls][64]
    float*  Psm = (float*)(sm + V_BYTES);             // temp, inside Xt region
    float*  bsm = Psm + 128 * 73;                     // conv1 bias (temp)
    __shared__ float part_sm[3][32];
    __shared__ float mean_sm[32];
    __shared__ int s_ycid[64], s_xcid[64];
    __shared__ uint32_t s_ycls[24], s_xcls[24];
    __shared__ int s_NY, s_NX;

    int tid = threadIdx.x, wid = tid >> 5, lane = tid & 31;
    int pair = blockIdx.x / 3;
    int rank = (int)ctarank();
    uint32_t xt_addr = smem_u32(sm) + V_BYTES;

    int TILE0 = (rank == 0) ? 0 : (rank == 1 ? 18 : 33);
    int NT    = (rank == 0) ? 19 : 16;
    int ROW0  = TILE0 * 16;
    int NR    = (rank == 0) ? 428 : (rank == 1 ? 380 : 372);
    int PI0   = (rank == 0) ? 0 : (rank == 1 ? 5 : 9);
    int NPI   = (rank == 0) ? 5 : 4;

    // ---- load SAT tables (transposed to [box*64+c][73]) + conv1 bias (temp region)
    for (int k = tid; k < 128 * 36; k += 512) {
        int u = k / 36, kk = k - u * 36;       // u = o*2 + box
        int o = u >> 1, box = u & 1;
        Psm[(box * 64 + o) * 73 + kk] = g_P[k];
    }
    if (tid < 64) bsm[tid] = conv1_b[tid];

    // ---- per-pair box geometry (exact)
    int bidx = pair >> 6;
    int i0 = object_pairs[pair * 2 + 0];
    int i1 = object_pairs[pair * 2 + 1];
    const float* p0 = bboxes + (bidx * NOBJ + i0) * 4;
    const float* p1 = bboxes + (bidx * NOBJ + i1) * 4;
    float b0x1 = p0[0], b0y1 = p0[1], b0x2 = p0[2], b0y2 = p0[3];
    float b1x1 = p1[0], b1y1 = p1[1], b1x2 = p1[2], b1y2 = p1[3];
    float ux1 = fminf(b0x1, b1x1), uy1 = fminf(b0y1, b1y1);
    float ux2 = fmaxf(b0x2, b1x2), uy2 = fmaxf(b0y2, b1y2);
    float uw = fmaxf(ux2 - ux1, 1e-6f), uh = fmaxf(uy2 - uy1, 1e-6f);
    int Ax0 = lo_int((b0x1 - ux1) / uw * 64.0f), Ay0 = lo_int((b0y1 - uy1) / uh * 64.0f);
    int Bx0 = hi_int((b0x2 - ux1) / uw * 64.0f), By0 = hi_int((b0y2 - uy1) / uh * 64.0f);
    int Ax1 = lo_int((b1x1 - ux1) / uw * 64.0f), Ay1 = lo_int((b1y1 - uy1) / uh * 64.0f);
    int Bx1 = hi_int((b1x2 - ux1) / uw * 64.0f), By1 = hi_int((b1y2 - uy1) / uh * 64.0f);

    // ---- class staircases (2 threads)
    if (tid == 0) {
        int n = 0; uint32_t prev = 0xFFFFFFFFu;
        for (int i2 = 0; i2 < 60; i2++) {
            int pl0 = min(max(Ay0 - i2, 0), 5), ph0 = max(min(max(By0 - i2 + 1, 0), 5), pl0);
            int pl1 = min(max(Ay1 - i2, 0), 5), ph1 = max(min(max(By1 - i2 + 1, 0), 5), pl1);
            uint32_t tup = (uint32_t)pl0 | ((uint32_t)ph0 << 4) | ((uint32_t)pl1 << 8) | ((uint32_t)ph1 << 12);
            if (tup != prev) { s_ycls[n++] = tup; prev = tup; }
            s_ycid[i2] = n - 1;
        }
        s_NY = n;
    } else if (tid == 32) {
        int n = 0; uint32_t prev = 0xFFFFFFFFu;
        for (int j2 = 0; j2 < 60; j2++) {
            int ql0 = min(max(Ax0 - j2, 0), 5), qh0 = max(min(max(Bx0 - j2 + 1, 0), 5), ql0);
            int ql1 = min(max(Ax1 - j2, 0), 5), qh1 = max(min(max(Bx1 - j2 + 1, 0), 5), ql1);
            uint32_t tup = (uint32_t)ql0 | ((uint32_t)qh0 << 4) | ((uint32_t)ql1 << 8) | ((uint32_t)qh1 << 12);
            if (tup != prev) { s_xcls[n++] = tup; prev = tup; }
            s_xcid[j2] = n - 1;
        }
        s_NX = n;
    }
    __syncthreads();

    // ---- class LUT V[yc*NX+xc][c] (fp16, bias folded); same 8-term order as before
    int NX = s_NX, NYX = s_NY * NX;
    for (int cls = wid; cls < NYX; cls += 16) {
        int yc = (int)((unsigned)cls / (unsigned)NX);
        int xc = cls - yc * NX;
        uint32_t ty = s_ycls[yc], tx = s_xcls[xc];
        int pl0 = ty & 15, ph0 = (ty >> 4) & 15, pl1 = (ty >> 8) & 15, ph1 = (ty >> 12) & 15;
        int ql0 = tx & 15, qh0 = (tx >> 4) & 15, ql1 = (tx >> 8) & 15, qh1 = (tx >> 12) & 15;
        #pragma unroll
        for (int ch = 0; ch < 2; ch++) {
            int c = lane + ch * 32;
            const float* P0 = Psm + c * 73;
            const float* P1 = Psm + (64 + c) * 73;
            float vv = P0[ph0 * 6 + qh0] - P0[pl0 * 6 + qh0] - P0[ph0 * 6 + ql0] + P0[pl0 * 6 + ql0]
                     + P1[ph1 * 6 + qh1] - P1[pl1 * 6 + qh1] - P1[ph1 * 6 + ql1] + P1[pl1 * 6 + ql1]
                     + bsm[c];
            Vh[cls * 64 + c] = __float2half(vv);
        }
    }
    __syncthreads();

    // ---- build Xt window rows (lr local; global r = ROW0 + lr); P region now dead
    for (int lr = wid; lr < NR; lr += 16) {
        int r = ROW0 + lr;
        int i = (int)((unsigned)r / 30u);
        int j = r - i * 30;
        int ycA = s_ycid[2 * i], ycB = s_ycid[2 * i + 1];
        int xcA = s_xcid[2 * j], xcB = s_xcid[2 * j + 1];
        int b00 = (ycA * NX + xcA) * 64, b01 = (ycA * NX + xcB) * 64;
        int b10 = (ycB * NX + xcA) * 64, b11 = (ycB * NX + xcB) * 64;
        __half v1 = __hmax(__hmax(Vh[b00 + lane], Vh[b01 + lane]),
                           __hmax(Vh[b10 + lane], Vh[b11 + lane]));
        int l2 = lane + 32;
        __half v2 = __hmax(__hmax(Vh[b00 + l2], Vh[b01 + l2]),
                           __hmax(Vh[b10 + l2], Vh[b11 + l2]));
        uint32_t my = (uint32_t)__half_as_ushort(v1) | ((uint32_t)__half_as_ushort(v2) << 16);
        uint32_t ot = __shfl_xor_sync(0xffffffffu, my, 1);
        uint32_t val; int slot;
        if ((lane & 1) == 0) { slot = lane >> 1;        val = (my & 0xffffu) | (ot << 16); }
        else                 { slot = 16 + (lane >> 1); val = (ot >> 16) | (my & 0xffff0000u); }
        *(uint32_t*)(sm + V_BYTES + lr * 128
                     + (((uint32_t)slot * 4) ^ ((uint32_t)(lr & 7) * 16))) = val;
    }
    __syncthreads();

    // ---- mainloop: 25 taps x 4 kt; 2 tile-slots per warp
    float d[2][4][4];
    #pragma unroll
    for (int s = 0; s < 2; s++)
        #pragma unroll
        for (int nt = 0; nt < 4; nt++)
            #pragma unroll
            for (int e = 0; e < 4; e++) d[s][nt][e] = 0.0f;

    int l15 = lane & 15, lh = lane >> 4;
    int nrm1 = NR - 1;
    #pragma unroll 1
    for (int tap = 0; tap < 25; tap++) {
        int off = (tap / 5) * 30 + (tap % 5);
        #pragma unroll
        for (int kt = 0; kt < 4; kt++) {
            const uint4* wf = g_wF4 + (tap * 4 + kt) * 64 + lane;
            uint4 B0 = __ldg(wf);
            uint4 B1 = __ldg(wf + 32);
            #pragma unroll
            for (int s = 0; s < 2; s++) {
                int wslot = wid + s * 16;
                if (wslot < NT) {
                    int lr = off + wslot * 16 + l15;     // row - ROW0
                    if (lr > nrm1) lr = nrm1;            // only feeds discarded outputs
                    uint32_t aaddr = xt_addr + (uint32_t)lr * 128
                                   + (((uint32_t)(kt * 32 + lh * 16)) ^ ((uint32_t)(lr & 7) * 16));
                    uint32_t a[4];
                    ldsm_x4(a, aaddr);
                    mma16816(d[s][0], a, B0.x, B0.y);
                    mma16816(d[s][1], a, B0.z, B0.w);
                    mma16816(d[s][2], a, B1.x, B1.y);
                    mma16816(d[s][3], a, B1.z, B1.w);
                }
            }
        }
    }
    __syncthreads();   // Xt + V dead; Y overlays from offset 0

    // ---- scatter D -> Y[o][i*26+j] (global indexing, private per CTA)
    float* Yf = (float*)sm;
    int g = lane >> 2, c0 = (lane & 3) * 2;
    #pragma unroll
    for (int s = 0; s < 2; s++) {
        int wslot = wid + s * 16;
        if (wslot < NT) {
            int tile = TILE0 + wslot;
            #pragma unroll
            for (int nt = 0; nt < 4; nt++) {
                int o = nt * 8 + c0;
                #pragma unroll
                for (int half = 0; half < 2; half++) {
                    int m = tile * 16 + g + half * 8;
                    int i = (int)((unsigned)m / 30u);
                    int j = m - i * 30;
                    if (i < 26 && j < 26) {
                        Yf[o * 676 + i * 26 + j]       = d[s][nt][half * 2 + 0];
                        Yf[(o + 1) * 676 + i * 26 + j] = d[s][nt][half * 2 + 1];
                    }
                }
            }
        }
    }
    __syncthreads();

    // ---- pool2 (2x2 max) + partial spatial sum over own pi rows; warp per 2 o
    int NW = NPI * 13;
    #pragma unroll
    for (int oo = 0; oo < 2; oo++) {
        int o = wid * 2 + oo;
        float ssum = 0.0f;
        for (int idx = lane; idx < NW; idx += 32) {
            int pil = idx / 13, pj = idx - pil * 13;
            int pi = PI0 + pil;
            const float* b = Yf + (o * 26 + 2 * pi) * 26 + 2 * pj;
            ssum += fmaxf(fmaxf(b[0], b[1]), fmaxf(b[26], b[27]));
        }
        #pragma unroll
        for (int offs = 16; offs; offs >>= 1) ssum += __shfl_down_sync(0xffffffffu, ssum, offs);
        if (lane == 0) {
            if (rank == 0) part_sm[0][o] = ssum;
            else st_cluster_f32(smem_u32(&part_sm[rank][o]), 0, ssum);
        }
    }
    __syncthreads();
    CLUSTER_SYNC();    // partials visible in rank0

    if (rank == 0) {
        if (tid < 32)
            mean_sm[tid] = (part_sm[0][tid] + part_sm[1][tid] + part_sm[2][tid])
                         * (1.0f / 169.0f) + __ldg(&conv2_b[tid]);
        __syncthreads();
        // ---- fc (32 -> 512) + relu : one output per thread
        int k = tid;
        float v = __ldg(&fc_b[k]);
        const float4* fw = (const float4*)(fc_w + k * 32);
        #pragma unroll
        for (int c4 = 0; c4 < 8; c4++) {
            float4 w4 = __ldg(&fw[c4]);
            v = fmaf(mean_sm[c4 * 4 + 0], w4.x, v);
            v = fmaf(mean_sm[c4 * 4 + 1], w4.y, v);
            v = fmaf(mean_sm[c4 * 4 + 2], w4.z, v);
            v = fmaf(mean_sm[c4 * 4 + 3], w4.w, v);
        }
        out[pair * 512 + k] = fmaxf(v, 0.0f);
    }
}

// ---------------- launch ----------------
extern "C" void kernel_launch(void* const* d_in, const int* in_sizes, int n_in,
                              void* d_out, int out_size) {
    const float* bboxes       = (const float*)d_in[0];
    const int*   object_pairs = (const int*)d_in[3];
    const float* conv1_w      = (const float*)d_in[4];
    const float* conv1_b      = (const float*)d_in[5];
    const float* conv2_w      = (const float*)d_in[6];
    const float* conv2_b      = (const float*)d_in[7];
    const float* fc_w         = (const float*)d_in[8];
    const float* fc_b         = (const float*)d_in[9];
    float* out = (float*)d_out;

    static int attr_set = 0;
    if (!attr_set) {
        cudaFuncSetAttribute(fused_kernel, cudaFuncAttributeMaxDynamicSharedMemorySize, DSMEM);
        attr_set = 1;
    }
    prep_kernel<<<(6400 + 128 + 255) / 256, 256>>>(conv2_w, conv1_w);
    fused_kernel<<<NPAIR * 3, 512, DSMEM>>>(bboxes, object_pairs, conv1_b, conv2_b,
                                            fc_w, fc_b, out);
}

// round 14
// speedup vs baseline: 1.4235x; 1.4235x over previous
#include <cuda_runtime.h>
#include <cuda_fp16.h>
#include <cstdint>
#include <math.h>
#include <float.h>

#define NPAIR 1024
#define NOBJ  32
#define NTHREADS 768
#define NWARPS   24

// pos grid: m = i*30 + j (pool1 30x30). Valid outputs i,j <= 25 -> m <= 775.
// rows read: m + p*30 + q <= 899 -> Xt rows 0..899.
#define XT_ROWS  900
#define XT_BYTES (XT_ROWS * 128)            // 115200: [row][64 ch f16], SW128 per 128B row
#define P_OFF    XT_BYTES                   // SAT tables, [box*64+c][pitch 73] floats
#define P_BYTES  (128 * 73 * 4)             // 37376
#define BIAS_OFF (P_OFF + P_BYTES)
#define V_OFF    (BIAS_OFF + 256)
#define V_HALFS  (441 * 64)                 // class LUT (<= 21*21 classes)
#define DSMEM    (V_OFF + V_HALFS * 2)      // 209280 ; Y (86528B) overlays Xt after mainloop

// ---------------- persistent prep scratch ----------------
__device__ float g_P[128 * 36];                        // conv1 SAT per (outch*2+box)
__device__ __align__(16) uint4 g_wF4[25 * 4 * 2 * 32]; // B-fragments [tap][kt][nt2][lane]

// ---------------- warp-mma helpers ----------------
__device__ __forceinline__ uint32_t smem_u32(const void* p) {
    uint32_t a;
    asm("{ .reg .u64 t; cvta.to.shared.u64 t, %1; cvt.u32.u64 %0, t; }" : "=r"(a) : "l"(p));
    return a;
}
__device__ __forceinline__ void ldsm_x4(uint32_t* a, uint32_t addr) {
    asm volatile("ldmatrix.sync.aligned.m8n8.x4.shared.b16 {%0,%1,%2,%3}, [%4];"
                 : "=r"(a[0]), "=r"(a[1]), "=r"(a[2]), "=r"(a[3]) : "r"(addr));
}
__device__ __forceinline__ void mma16816(float* d, const uint32_t* a, uint32_t b0, uint32_t b1) {
    asm volatile("mma.sync.aligned.m16n8k16.row.col.f32.f16.f16.f32 "
                 "{%0,%1,%2,%3}, {%4,%5,%6,%7}, {%8,%9}, {%0,%1,%2,%3};"
                 : "+f"(d[0]), "+f"(d[1]), "+f"(d[2]), "+f"(d[3])
                 : "r"(a[0]), "r"(a[1]), "r"(a[2]), "r"(a[3]), "r"(b0), "r"(b1));
}

// --------- exact integerization of mask intervals (proven) -----------
__device__ __forceinline__ int lo_int(float t) {
    int a = (int)ceilf(t - 0.5f);
    if ((float)a + 0.5f < t) a++;
    else if ((float)(a - 1) + 0.5f >= t) a--;
    return a;
}
__device__ __forceinline__ int hi_int(float t) {
    int b = (int)floorf(t - 0.5f);
    if ((float)b + 0.5f > t) b--;
    else if ((float)(b + 1) + 0.5f <= t) b++;
    return b;
}

// ---------------- K0: prep (unchanged, proven) ----------------
__global__ void prep_kernel(const float* __restrict__ conv2_w,
                            const float* __restrict__ conv1_w) {
    int idx = blockIdx.x * blockDim.x + threadIdx.x;
    if (idx < 6400) {
        int lane = idx & 31;
        int nt2  = (idx >> 5) & 1;
        int kt   = (idx >> 6) & 3;
        int tap  = idx >> 8;
        int c0 = kt * 16 + 2 * (lane & 3);
        int orow = lane >> 2;
        auto wv = [&](int o, int c) -> __half {
            return __float2half(conv2_w[(o * 64 + c) * 25 + tap]);
        };
        auto pk = [&](__half lo, __half hi) -> uint32_t {
            __half2 h = __halves2half2(lo, hi);
            return *(uint32_t*)&h;
        };
        int oe = (nt2 * 2) * 8 + orow;
        int oo = (nt2 * 2 + 1) * 8 + orow;
        uint4 u;
        u.x = pk(wv(oe, c0),     wv(oe, c0 + 1));
        u.y = pk(wv(oe, c0 + 8), wv(oe, c0 + 9));
        u.z = pk(wv(oo, c0),     wv(oo, c0 + 1));
        u.w = pk(wv(oo, c0 + 8), wv(oo, c0 + 9));
        g_wF4[((tap * 4 + kt) * 2 + nt2) * 32 + lane] = u;
    } else if (idx < 6400 + 128) {
        int u = idx - 6400;
        const float* w = conv1_w + u * 25;
        float P[36];
        #pragma unroll
        for (int k = 0; k < 6; k++) { P[k] = 0.0f; P[k * 6] = 0.0f; }
        for (int a = 1; a < 6; a++)
            for (int b = 1; b < 6; b++)
                P[a * 6 + b] = P[(a - 1) * 6 + b] + P[a * 6 + b - 1]
                             - P[(a - 1) * 6 + b - 1] + w[(a - 1) * 5 + (b - 1)];
        for (int k = 0; k < 36; k++) g_P[u * 36 + k] = P[k];
    }
}

// ---------------- K1: fused everything (768 threads, 24 warps) ----------------
__global__ __launch_bounds__(NTHREADS, 1) void fused_kernel(
    const float* __restrict__ bboxes, const int* __restrict__ object_pairs,
    const float* __restrict__ conv1_b, const float* __restrict__ conv2_b,
    const float* __restrict__ fc_w, const float* __restrict__ fc_b,
    float* __restrict__ out) {
    extern __shared__ char sm[];
    float*  Psm = (float*)(sm + P_OFF);     // [box*64+c][73]
    float*  bsm = (float*)(sm + BIAS_OFF);
    __half* Vh  = (__half*)(sm + V_OFF);    // [cls][64]
    __shared__ float mean_sm[32];
    __shared__ int s_ycid[64], s_xcid[64];
    __shared__ uint32_t s_ycls[24], s_xcls[24];
    __shared__ int s_NY, s_NX;

    int tid = threadIdx.x, wid = tid >> 5, lane = tid & 31;
    int pair = blockIdx.x;
    uint32_t xt_addr = smem_u32(sm);

    // ---- load SAT tables (transposed to [box*64+c][73]) + conv1 bias
    for (int k = tid; k < 128 * 36; k += NTHREADS) {
        int u = k / 36, kk = k - u * 36;        // u = o*2 + box
        int o = u >> 1, box = u & 1;
        Psm[(box * 64 + o) * 73 + kk] = g_P[k];
    }
    if (tid < 64) bsm[tid] = conv1_b[tid];

    // ---- per-pair box geometry (exact)
    int bidx = pair >> 6;
    int i0 = object_pairs[pair * 2 + 0];
    int i1 = object_pairs[pair * 2 + 1];
    const float* p0 = bboxes + (bidx * NOBJ + i0) * 4;
    const float* p1 = bboxes + (bidx * NOBJ + i1) * 4;
    float b0x1 = p0[0], b0y1 = p0[1], b0x2 = p0[2], b0y2 = p0[3];
    float b1x1 = p1[0], b1y1 = p1[1], b1x2 = p1[2], b1y2 = p1[3];
    float ux1 = fminf(b0x1, b1x1), uy1 = fminf(b0y1, b1y1);
    float ux2 = fmaxf(b0x2, b1x2), uy2 = fmaxf(b0y2, b1y2);
    float uw = fmaxf(ux2 - ux1, 1e-6f), uh = fmaxf(uy2 - uy1, 1e-6f);
    int Ax0 = lo_int((b0x1 - ux1) / uw * 64.0f), Ay0 = lo_int((b0y1 - uy1) / uh * 64.0f);
    int Bx0 = hi_int((b0x2 - ux1) / uw * 64.0f), By0 = hi_int((b0y2 - uy1) / uh * 64.0f);
    int Ax1 = lo_int((b1x1 - ux1) / uw * 64.0f), Ay1 = lo_int((b1y1 - uy1) / uh * 64.0f);
    int Bx1 = hi_int((b1x2 - ux1) / uw * 64.0f), By1 = hi_int((b1y2 - uy1) / uh * 64.0f);

    // ---- class staircases (2 threads; <= 21 classes each, hard bound)
    if (tid == 0) {
        int n = 0; uint32_t prev = 0xFFFFFFFFu;
        for (int i2 = 0; i2 < 60; i2++) {
            int pl0 = min(max(Ay0 - i2, 0), 5), ph0 = max(min(max(By0 - i2 + 1, 0), 5), pl0);
            int pl1 = min(max(Ay1 - i2, 0), 5), ph1 = max(min(max(By1 - i2 + 1, 0), 5), pl1);
            uint32_t tup = (uint32_t)pl0 | ((uint32_t)ph0 << 4) | ((uint32_t)pl1 << 8) | ((uint32_t)ph1 << 12);
            if (tup != prev) { s_ycls[n++] = tup; prev = tup; }
            s_ycid[i2] = n - 1;
        }
        s_NY = n;
    } else if (tid == 32) {
        int n = 0; uint32_t prev = 0xFFFFFFFFu;
        for (int j2 = 0; j2 < 60; j2++) {
            int ql0 = min(max(Ax0 - j2, 0), 5), qh0 = max(min(max(Bx0 - j2 + 1, 0), 5), ql0);
            int ql1 = min(max(Ax1 - j2, 0), 5), qh1 = max(min(max(Bx1 - j2 + 1, 0), 5), ql1);
            uint32_t tup = (uint32_t)ql0 | ((uint32_t)qh0 << 4) | ((uint32_t)ql1 << 8) | ((uint32_t)qh1 << 12);
            if (tup != prev) { s_xcls[n++] = tup; prev = tup; }
            s_xcid[j2] = n - 1;
        }
        s_NX = n;
    }
    __syncthreads();

    // ---- build class LUT V[yc*NX+xc][c] (fp16, bias folded). Same 8-term order.
    int NX = s_NX, NYX = s_NY * NX;
    for (int cls = wid; cls < NYX; cls += NWARPS) {
        int yc = (int)((unsigned)cls / (unsigned)NX);
        int xc = cls - yc * NX;
        uint32_t ty = s_ycls[yc], tx = s_xcls[xc];
        int pl0 = ty & 15, ph0 = (ty >> 4) & 15, pl1 = (ty >> 8) & 15, ph1 = (ty >> 12) & 15;
        int ql0 = tx & 15, qh0 = (tx >> 4) & 15, ql1 = (tx >> 8) & 15, qh1 = (tx >> 12) & 15;
        #pragma unroll
        for (int ch = 0; ch < 2; ch++) {
            int c = lane + ch * 32;
            const float* P0 = Psm + c * 73;           // box0
            const float* P1 = Psm + (64 + c) * 73;    // box1
            float vv = P0[ph0 * 6 + qh0] - P0[pl0 * 6 + qh0] - P0[ph0 * 6 + ql0] + P0[pl0 * 6 + ql0]
                     + P1[ph1 * 6 + qh1] - P1[pl1 * 6 + qh1] - P1[ph1 * 6 + ql1] + P1[pl1 * 6 + ql1]
                     + bsm[c];
            Vh[cls * 64 + c] = __float2half(vv);
        }
    }
    __syncthreads();

    // ---- build Xt rows: warp per row, 8 coalesced V loads + hmax + shuffle pack
    for (int r = wid; r < XT_ROWS; r += NWARPS) {
        int i = (int)((unsigned)r / 30u);
        int j = r - i * 30;
        int ycA = s_ycid[2 * i], ycB = s_ycid[2 * i + 1];
        int xcA = s_xcid[2 * j], xcB = s_xcid[2 * j + 1];
        int b00 = (ycA * NX + xcA) * 64, b01 = (ycA * NX + xcB) * 64;
        int b10 = (ycB * NX + xcA) * 64, b11 = (ycB * NX + xcB) * 64;
        __half v1 = __hmax(__hmax(Vh[b00 + lane], Vh[b01 + lane]),
                           __hmax(Vh[b10 + lane], Vh[b11 + lane]));
        int l2 = lane + 32;
        __half v2 = __hmax(__hmax(Vh[b00 + l2], Vh[b01 + l2]),
                           __hmax(Vh[b10 + l2], Vh[b11 + l2]));
        uint32_t my = (uint32_t)__half_as_ushort(v1) | ((uint32_t)__half_as_ushort(v2) << 16);
        uint32_t ot = __shfl_xor_sync(0xffffffffu, my, 1);
        uint32_t val; int slot;
        if ((lane & 1) == 0) { slot = lane >> 1;        val = (my & 0xffffu) | (ot << 16); }
        else                 { slot = 16 + (lane >> 1); val = (ot >> 16) | (my & 0xffff0000u); }
        *(uint32_t*)(sm + r * 128 + (((uint32_t)slot * 4) ^ ((uint32_t)(r & 7) * 16))) = val;
    }
    __syncthreads();

    // ---- mainloop: 25 taps x 4 kt; A via ldsm, B fragments via LDG; 3 tile-slots/warp
    float d[3][4][4];
    #pragma unroll
    for (int t = 0; t < 3; t++)
        #pragma unroll
        for (int nt = 0; nt < 4; nt++)
            #pragma unroll
            for (int e = 0; e < 4; e++) d[t][nt][e] = 0.0f;

    int l15 = lane & 15, lh = lane >> 4;
    #pragma unroll 1
    for (int tap = 0; tap < 25; tap++) {
        int off = (tap / 5) * 30 + (tap % 5);
        #pragma unroll
        for (int kt = 0; kt < 4; kt++) {
            const uint4* wf = g_wF4 + (tap * 4 + kt) * 64 + lane;
            uint4 B0 = __ldg(wf);
            uint4 B1 = __ldg(wf + 32);
            #pragma unroll
            for (int t = 0; t < 3; t++) {
                int tile = wid + t * NWARPS;
                if (tile < 49) {
                    int row = off + tile * 16 + l15;
                    if (row > 899) row = 899;    // only feeds discarded outputs
                    uint32_t aaddr = xt_addr + (uint32_t)row * 128
                                   + (((uint32_t)(kt * 32 + lh * 16)) ^ ((uint32_t)(row & 7) * 16));
                    uint32_t a[4];
                    ldsm_x4(a, aaddr);
                    mma16816(d[t][0], a, B0.x, B0.y);
                    mma16816(d[t][1], a, B0.z, B0.w);
                    mma16816(d[t][2], a, B1.x, B1.y);
                    mma16816(d[t][3], a, B1.z, B1.w);
                }
            }
        }
    }
    __syncthreads();   // Xt dead; Y overlays it

    // ---- scatter D -> Y[o][i*26+j]
    float* Yf = (float*)sm;
    int g = lane >> 2, c0 = (lane & 3) * 2;
    #pragma unroll
    for (int t = 0; t < 3; t++) {
        int tile = wid + t * NWARPS;
        if (tile < 49) {
            #pragma unroll
            for (int nt = 0; nt < 4; nt++) {
                int o = nt * 8 + c0;
                #pragma unroll
                for (int half = 0; half < 2; half++) {
                    int m = tile * 16 + g + half * 8;
                    int i = (int)((unsigned)m / 30u);
                    int j = m - i * 30;
                    if (i < 26 && j < 26) {
                        Yf[o * 676 + i * 26 + j]       = d[t][nt][half * 2 + 0];
                        Yf[(o + 1) * 676 + i * 26 + j] = d[t][nt][half * 2 + 1];
                    }
                }
            }
        }
    }
    __syncthreads();

    // ---- pool2 (2x2 max) + mean + conv2 bias ; warps 0..15, 2 o each
    if (wid < 16) {
        #pragma unroll
        for (int oo = 0; oo < 2; oo++) {
            int o = wid * 2 + oo;
            float ssum = 0.0f;
            for (int idx = lane; idx < 169; idx += 32) {
                int pi = idx / 13, pj = idx - pi * 13;
                const float* b = Yf + (o * 26 + 2 * pi) * 26 + 2 * pj;
                ssum += fmaxf(fmaxf(b[0], b[1]), fmaxf(b[26], b[27]));
            }
            #pragma unroll
            for (int offs = 16; offs; offs >>= 1) ssum += __shfl_down_sync(0xffffffffu, ssum, offs);
            if (lane == 0) mean_sm[o] = ssum * (1.0f / 169.0f) + __ldg(&conv2_b[o]);
        }
    }
    __syncthreads();

    // ---- fc (32 -> 512) + relu : one output per thread (first 512 threads)
    if (tid < 512) {
        int k = tid;
        float v = __ldg(&fc_b[k]);
        const float4* fw = (const float4*)(fc_w + k * 32);
        #pragma unroll
        for (int c4 = 0; c4 < 8; c4++) {
            float4 w4 = __ldg(&fw[c4]);
            v = fmaf(mean_sm[c4 * 4 + 0], w4.x, v);
            v = fmaf(mean_sm[c4 * 4 + 1], w4.y, v);
            v = fmaf(mean_sm[c4 * 4 + 2], w4.z, v);
            v = fmaf(mean_sm[c4 * 4 + 3], w4.w, v);
        }
        out[pair * 512 + k] = fmaxf(v, 0.0f);
    }
}

// ---------------- launch ----------------
extern "C" void kernel_launch(void* const* d_in, const int* in_sizes, int n_in,
                              void* d_out, int out_size) {
    const float* bboxes       = (const float*)d_in[0];
    const int*   object_pairs = (const int*)d_in[3];
    const float* conv1_w      = (const float*)d_in[4];
    const float* conv1_b      = (const float*)d_in[5];
    const float* conv2_w      = (const float*)d_in[6];
    const float* conv2_b      = (const float*)d_in[7];
    const float* fc_w         = (const float*)d_in[8];
    const float* fc_b         = (const float*)d_in[9];
    float* out = (float*)d_out;

    static int attr_set = 0;
    if (!attr_set) {
        cudaFuncSetAttribute(fused_kernel, cudaFuncAttributeMaxDynamicSharedMemorySize, DSMEM);
        attr_set = 1;
    }
    prep_kernel<<<(6400 + 128 + 255) / 256, 256>>>(conv2_w, conv1_w);
    fused_kernel<<<NPAIR, NTHREADS, DSMEM>>>(bboxes, object_pairs, conv1_b, conv2_b,
                                             fc_w, fc_b, out);
}